// round 5
// baseline (speedup 1.0000x reference)
#include <cuda_runtime.h>

#define BB 64      // batch
#define SS 512     // sequence length
#define EE 256     // embedding dim
#define HH 512     // hidden

typedef unsigned long long u64;
typedef unsigned int u32;

// ---------------------------------------------------------------------------
// Device globals
// ---------------------------------------------------------------------------
__device__ u32 g_wf[128];            // per-CTA h write-flags (monotonic across replays)
__device__ float g_h[4][HH * BB];    // h ring: slot s&3 holds h(s), layout [k][b]

// ---------------------------------------------------------------------------
// f32x2 helpers (packed FFMA2 -- only reachable via PTX)
// ---------------------------------------------------------------------------
__device__ __forceinline__ u64 fma2(u64 a, u64 b, u64 c) {
    u64 d; asm("fma.rn.f32x2 %0, %1, %2, %3;" : "=l"(d) : "l"(a), "l"(b), "l"(c)); return d;
}
__device__ __forceinline__ u64 pack2(float x, float y) {
    u64 d; asm("mov.b64 %0, {%1, %2};" : "=l"(d) : "f"(x), "f"(y)); return d;
}
__device__ __forceinline__ float sigf(float x) { return 1.f / (1.f + __expf(-x)); }
__device__ __forceinline__ float tanh_f(float x) { return 2.f / (1.f + __expf(-2.f * x)) - 1.f; }

// SMEM layout (float offsets)
#define OFF_WREC 0        // 8192  : W_hh pairs {w_jA,w_jB} (32KB)
#define OFF_SCP  8192     // 8192  : reduce scratch (32KB, float2[4096])
#define OFF_WP   16384    // 8192  : W_ih pairs duplicated (32KB, float2[4096])
#define OFF_ES   24576    // 4224  : emb chunk [64k][66] (16.5KB)
#define OFF_RING 28800    // 4096  : xg ring, 4 slots x [16g][64b] (16KB)
#define OFF_SROW 32896    // 64    : emb row indices (int)
#define OFF_BSUM 32960    // 16    : b_ih+b_hh per local gate row
#define OFF_MISC 32976    // 4     : [0]=is64 [1]=prodc [2]=consc [3]=flag base
#define SMEM_FLOATS 32980

// ---------------------------------------------------------------------------
// Fused persistent kernel: 128 CTAs x 512 threads.
//   warps 0-7  : LSTM recurrence (f32x2 GEMM, dataflow-synced via g_wf flags)
//   warps 8-15 : xg producer (emb gather + W_ih GEMM for THIS CTA's 16 gate
//                rows, into a local 4-slot SMEM ring)
// No grid barrier. h ring depth 4 makes flag-order sufficient for safety.
// ---------------------------------------------------------------------------
__global__ void __launch_bounds__(512, 1) fused_lstm(
    const void* __restrict__ seq, const float* __restrict__ emb,
    const float* __restrict__ Wih, const float* __restrict__ Whh,
    const float* __restrict__ bih, const float* __restrict__ bhh,
    float* __restrict__ out, int write_c)
{
    extern __shared__ float smf[];
    const int tid = threadIdx.x;
    const int cta = blockIdx.x;
    const int j0  = cta * 4;

    u32 smbase;
    asm("{ .reg .u64 t; cvta.to.shared.u64 t, %1; cvt.u32.u64 %0, t; }"
        : "=r"(smbase) : "l"(smf));
    const u32 addr_prod = smbase + (OFF_MISC + 1) * 4;
    const u32 addr_cons = smbase + (OFF_MISC + 2) * 4;
    u32* miscp = (u32*)(smf + OFF_MISC);

    if (tid == 0) {
        miscp[1] = 0u;                 // prodc
        miscp[2] = 0u;                 // consc
        miscp[3] = g_wf[cta];          // flag base (monotonic, equal across CTAs)
    }

    if (tid < 256) {
        // stage W_hh pairs: stream st = g*2+jp covers rows (g*H + j0+2jp, +1)
        float* Ws = smf + OFF_WREC;
        #pragma unroll
        for (int st = 0; st < 8; st++) {
            int g = st >> 1, jp = st & 1;
            const float* r0 = Whh + (size_t)(g * HH + j0 + 2 * jp) * HH;
            const float* r1 = r0 + HH;
            #pragma unroll
            for (int i = 0; i < 2; i++) {
                int k = tid + i * 256;
                *(float2*)&Ws[(st * 512 + k) * 2] = make_float2(r0[k], r1[k]);
            }
        }
    } else {
        const int pt = tid - 256;
        if (pt == 0) miscp[0] = 1u;            // is64
        asm volatile("bar.sync 2, 256;" ::: "memory");
        if (pt < 64 && ((const u32*)seq)[2 * pt + 1] != 0u) miscp[0] = 0u;
        // stage W_ih pairs (duplicated {w,w}) for our 16 gate rows
        {
            int gl = pt >> 4, kseg = pt & 15;
            int row = (gl >> 2) * HH + j0 + (gl & 3);
            const float* wsrc = Wih + (size_t)row * EE + kseg * 16;
            float2* wdst = (float2*)(smf + OFF_WP) + gl * 256 + kseg * 16;
            #pragma unroll
            for (int i = 0; i < 4; i++) {
                float4 v = *(const float4*)(wsrc + i * 4);
                wdst[i * 4 + 0] = make_float2(v.x, v.x);
                wdst[i * 4 + 1] = make_float2(v.y, v.y);
                wdst[i * 4 + 2] = make_float2(v.z, v.z);
                wdst[i * 4 + 3] = make_float2(v.w, v.w);
            }
        }
        if (pt < 16) {
            int row = (pt >> 2) * HH + j0 + (pt & 3);
            smf[OFF_BSUM + pt] = bih[row] + bhh[row];
        }
    }
    __syncthreads();   // the ONLY full-block sync

    if (tid < 256) {
        // ================= recurrence (warps 0-7) =================
        const float* Ws = smf + OFF_WREC;
        float2* scp = (float2*)(smf + OFF_SCP);
        const int wi = tid >> 5, lane = tid & 31;
        const int kbase = wi * 64;
        const int b = tid & 63, jj = tid >> 6, j = j0 + jj;
        const int jp_r = jj >> 1, comp = jj & 1, bh_r = b >> 5, lane_r = b & 31;
        const u32 base = miscp[3];
        float c_reg = 0.f, h_val = 0.f;

        #pragma unroll 1
        for (int s = 0; s < SS; s++) {
            // wait for local xg slice s
            u32 pv;
            do { asm volatile("ld.acquire.cta.shared.u32 %0, [%1];"
                              : "=r"(pv) : "r"(addr_prod)); }
            while ((int)(pv - (u32)(s + 1)) < 0);

            float xgv[4];
            const float* ring = smf + OFF_RING + (s & 3) * 1024;
            #pragma unroll
            for (int q = 0; q < 4; q++)
                xgv[q] = ring[(q * 4 + jj) * 64 + b];

            u64 acc[8][2];
            #pragma unroll
            for (int st = 0; st < 8; st++) { acc[st][0] = 0ull; acc[st][1] = 0ull; }

            if (s > 0) {
                // wait only for the 16 producer CTAs of OUR k-range
                const u32 target = base + (u32)s;
                int ok;
                do {
                    ok = 1;
                    if (lane < 16) {
                        u32 f;
                        asm volatile("ld.acquire.gpu.global.u32 %0, [%1];"
                                     : "=r"(f) : "l"(&g_wf[wi * 16 + lane]));
                        ok = ((int)(f - target) >= 0);
                    }
                } while (__all_sync(0xffffffffu, ok) == 0);

                const float* hsrc = g_h[(s - 1) & 3];
                float hreg[2][32];
                #pragma unroll
                for (int i = 0; i < 16; i++) {
                    hreg[0][i]      = __ldcg(&hsrc[(kbase + i) * 64 + lane]);
                    hreg[0][16 + i] = __ldcg(&hsrc[(kbase + i) * 64 + 32 + lane]);
                }
                #pragma unroll
                for (int c = 0; c < 4; c++) {
                    const int cur = c & 1, nxt = cur ^ 1;
                    if (c < 3) {
                        const int kn = kbase + (c + 1) * 16;
                        #pragma unroll
                        for (int i = 0; i < 16; i++) {
                            hreg[nxt][i]      = __ldcg(&hsrc[(kn + i) * 64 + lane]);
                            hreg[nxt][16 + i] = __ldcg(&hsrc[(kn + i) * 64 + 32 + lane]);
                        }
                    }
                    const int kg0 = kbase + c * 16;
                    #pragma unroll
                    for (int kk = 0; kk < 16; kk += 2) {
                        const int kg = kg0 + kk;
                        u64 dA0 = pack2(hreg[cur][kk],          hreg[cur][kk]);
                        u64 dB0 = pack2(hreg[cur][16 + kk],     hreg[cur][16 + kk]);
                        u64 dA1 = pack2(hreg[cur][kk + 1],      hreg[cur][kk + 1]);
                        u64 dB1 = pack2(hreg[cur][16 + kk + 1], hreg[cur][16 + kk + 1]);
                        #pragma unroll
                        for (int st = 0; st < 8; st++) {
                            ulonglong2 wv = *(const ulonglong2*)&Ws[(st * 512 + kg) * 2];
                            acc[st][0] = fma2(dA0, wv.x, acc[st][0]);
                            acc[st][1] = fma2(dB0, wv.x, acc[st][1]);
                            acc[st][0] = fma2(dA1, wv.y, acc[st][0]);
                            acc[st][1] = fma2(dB1, wv.y, acc[st][1]);
                        }
                    }
                }
            }

            // partials -> scratch [st][bh][kr][lane]
            #pragma unroll
            for (int st = 0; st < 8; st++) {
                scp[((st * 2 + 0) * 8 + wi) * 32 + lane] = *(float2*)&acc[st][0];
                scp[((st * 2 + 1) * 8 + wi) * 32 + lane] = *(float2*)&acc[st][1];
            }
            asm volatile("bar.sync 1, 256;" ::: "memory");

            float gt[4];
            #pragma unroll
            for (int g = 0; g < 4; g++) {
                int st = g * 2 + jp_r;
                const float2* rb = &scp[((st * 2 + bh_r) * 8) * 32 + lane_r];
                float sx = 0.f, sy = 0.f;
                #pragma unroll
                for (int kr = 0; kr < 8; kr++) { float2 p = rb[kr * 32]; sx += p.x; sy += p.y; }
                gt[g] = (comp ? sy : sx) + xgv[g];
            }
            float ig = sigf(gt[0]), fg = sigf(gt[1]);
            float gg = tanh_f(gt[2]), og = sigf(gt[3]);
            c_reg = fg * c_reg + ig * gg;
            h_val = og * tanh_f(c_reg);

            __stcg(&g_h[s & 3][j * 64 + b], h_val);
            asm volatile("bar.sync 1, 256;" ::: "memory");
            if (tid == 0) {
                asm volatile("st.release.cta.shared.u32 [%0], %1;"
                             :: "r"(addr_cons), "r"((u32)(s + 1)) : "memory");
                asm volatile("red.release.gpu.global.add.u32 [%0], %1;"
                             :: "l"(&g_wf[cta]), "r"(1u) : "memory");
            }
        }

        out[b * HH + j] = h_val;
        if (write_c) out[BB * HH + b * HH + j] = c_reg;
    } else {
        // ================= xg producer (warps 8-15) =================
        const int pt = tid - 256;
        const int wp = pt >> 5, pl = pt & 31;
        const int gl0 = wp * 2, gl1 = wp * 2 + 1;
        const int bq = pt & 63, kq = pt >> 6;
        int* srow = (int*)(smf + OFF_SROW);
        float* es = smf + OFF_ES;
        const float2* Wp = (const float2*)(smf + OFF_WP);
        const int is64 = (int)miscp[0];
        const u64 bs0 = pack2(smf[OFF_BSUM + gl0], smf[OFF_BSUM + gl0]);
        const u64 bs1 = pack2(smf[OFF_BSUM + gl1], smf[OFF_BSUM + gl1]);

        #pragma unroll 1
        for (int s = 0; s < SS; s++) {
            if (pt < 64) {
                int idx = is64 ? (int)((const long long*)seq)[pt * SS + s]
                               : ((const int*)seq)[pt * SS + s];
                srow[pt] = idx;
            }
            u64 a0 = bs0, a1 = bs1;
            #pragma unroll
            for (int kc = 0; kc < 4; kc++) {
                asm volatile("bar.sync 2, 256;" ::: "memory");
                {   // stage emb chunk [64k][64b] -> es (stride 66)
                    const float* er = emb + (size_t)srow[bq] * EE + kc * 64 + kq * 16;
                    #pragma unroll
                    for (int i = 0; i < 4; i++) {
                        float4 v = *(const float4*)(er + i * 4);
                        int klb = kq * 16 + i * 4;
                        es[(klb + 0) * 66 + bq] = v.x;
                        es[(klb + 1) * 66 + bq] = v.y;
                        es[(klb + 2) * 66 + bq] = v.z;
                        es[(klb + 3) * 66 + bq] = v.w;
                    }
                }
                asm volatile("bar.sync 2, 256;" ::: "memory");
                const int kgb = kc * 64;
                #pragma unroll
                for (int kl = 0; kl < 64; kl += 2) {
                    u64 e0 = *(const u64*)&es[kl * 66 + 2 * pl];
                    u64 e1 = *(const u64*)&es[(kl + 1) * 66 + 2 * pl];
                    const int kg = kgb + kl;
                    u64 w00 = *(const u64*)&Wp[gl0 * 256 + kg];
                    u64 w01 = *(const u64*)&Wp[gl0 * 256 + kg + 1];
                    u64 w10 = *(const u64*)&Wp[gl1 * 256 + kg];
                    u64 w11 = *(const u64*)&Wp[gl1 * 256 + kg + 1];
                    a0 = fma2(e0, w00, a0); a0 = fma2(e1, w01, a0);
                    a1 = fma2(e0, w10, a1); a1 = fma2(e1, w11, a1);
                }
            }
            if (s >= 4) {   // ring backpressure (depth 4)
                u32 cv;
                do { asm volatile("ld.acquire.cta.shared.u32 %0, [%1];"
                                  : "=r"(cv) : "r"(addr_cons)); }
                while ((int)(cv - (u32)(s - 3)) < 0);
            }
            float* ring = smf + OFF_RING + (s & 3) * 1024;
            *(u64*)&ring[gl0 * 64 + 2 * pl] = a0;
            *(u64*)&ring[gl1 * 64 + 2 * pl] = a1;
            asm volatile("bar.sync 2, 256;" ::: "memory");
            if (pt == 0)
                asm volatile("st.release.cta.shared.u32 [%0], %1;"
                             :: "r"(addr_prod), "r"((u32)(s + 1)) : "memory");
        }
    }
}

// ---------------------------------------------------------------------------
// kernel_launch: single fused launch
// ---------------------------------------------------------------------------
extern "C" void kernel_launch(void* const* d_in, const int* in_sizes, int n_in,
                              void* d_out, int out_size)
{
    const void*  seq = d_in[0];
    const float* emb = (const float*)d_in[1];
    const float* Wih = (const float*)d_in[2];
    const float* Whh = (const float*)d_in[3];
    const float* bih = (const float*)d_in[4];
    const float* bhh = (const float*)d_in[5];
    float* out = (float*)d_out;

    (void)in_sizes; (void)n_in;
    int write_c = (out_size >= 2 * BB * HH) ? 1 : 0;

    static const int kSmem = SMEM_FLOATS * (int)sizeof(float);   // ~128.8 KB
    cudaFuncSetAttribute(fused_lstm, cudaFuncAttributeMaxDynamicSharedMemorySize, kSmem);

    fused_lstm<<<HH / 4, 512, kSmem>>>(seq, emb, Wih, Whh, bih, bhh, out, write_c);
}

// round 6
// speedup vs baseline: 1.5129x; 1.5129x over previous
#include <cuda_runtime.h>

#define BB 64      // batch
#define SS 512     // sequence length
#define EE 256     // embedding dim
#define HH 512     // hidden
#define GG 2048    // 4*H gate rows

typedef unsigned long long u64;
typedef unsigned int u32;

// ---------------------------------------------------------------------------
// Device globals
// ---------------------------------------------------------------------------
__device__ u32 g_wf[128];                     // per-CTA h write-flags (monotonic)
__device__ float g_xg[SS * GG * BB];          // x_gates [s][g][b]
__device__ float g_h[4][HH * BB];             // h ring: slot s&3 = h(s), [k][b]

// ---------------------------------------------------------------------------
// f32x2 helpers (packed FFMA2 -- only reachable via PTX)
// ---------------------------------------------------------------------------
__device__ __forceinline__ u64 fma2(u64 a, u64 b, u64 c) {
    u64 d; asm("fma.rn.f32x2 %0, %1, %2, %3;" : "=l"(d) : "l"(a), "l"(b), "l"(c)); return d;
}
__device__ __forceinline__ u64 pack2(float x, float y) {
    u64 d; asm("mov.b64 %0, {%1, %2};" : "=l"(d) : "f"(x), "f"(y)); return d;
}
__device__ __forceinline__ float2 unpack2(u64 v) {
    float2 r; asm("mov.b64 {%0, %1}, %2;" : "=f"(r.x), "=f"(r.y) : "l"(v)); return r;
}
__device__ __forceinline__ float sigf(float x) { return 1.f / (1.f + __expf(-x)); }
__device__ __forceinline__ float tanh_f(float x) { return 2.f / (1.f + __expf(-2.f * x)) - 1.f; }

// ---------------------------------------------------------------------------
// Phase A: x_gates[s][g][b] = emb[seq[b][s]] . W_ih[g] + b_ih[g] + b_hh[g]
// (unchanged from R4: 128x64 tile, BK=16, 8Mx4N f32x2 micro, conflict-free)
// ---------------------------------------------------------------------------
__global__ void __launch_bounds__(256) xgates_gemm(
    const void* __restrict__ seq,
    const float* __restrict__ emb,
    const float* __restrict__ Wih,
    const float* __restrict__ bih,
    const float* __restrict__ bhh)
{
    __shared__ float  As[16][132];   // [k][m]
    __shared__ float2 Bs2[16][66];   // [k][j_local] duplicated {w,w}
    __shared__ int rows[128];
    __shared__ int s_is64;

    const int tid = threadIdx.x;
    const int s0 = blockIdx.y * 2;
    const int g0 = blockIdx.x * 64;

    if (tid == 0) s_is64 = 1;
    __syncthreads();
    if (tid < 64) {
        if (((const u32*)seq)[2 * tid + 1] != 0u) s_is64 = 0;
    }
    __syncthreads();
    if (tid < 128) {
        int b = tid & 63, sl = tid >> 6;
        int idx;
        if (s_is64) idx = (int)((const long long*)seq)[b * SS + s0 + sl];
        else        idx = ((const int*)seq)[b * SS + s0 + sl];
        rows[tid] = idx;
    }
    __syncthreads();

    const int tx = tid & 15;
    const int ty = tid >> 4;
    const int arow = tid >> 1;
    const int ak   = (tid & 1) * 8;
    const int wrow = tid >> 2;
    const int wk   = (tid & 3) * 4;

    u64 cc[4][4];
    #pragma unroll
    for (int p = 0; p < 4; p++)
        #pragma unroll
        for (int jn = 0; jn < 4; jn++) cc[p][jn] = 0ull;

    for (int k0 = 0; k0 < EE; k0 += 16) {
        const float* ap = emb + (size_t)rows[arow] * EE + k0 + ak;
        float4 a0 = *(const float4*)ap;
        float4 a1 = *(const float4*)(ap + 4);
        As[ak + 0][arow] = a0.x; As[ak + 1][arow] = a0.y;
        As[ak + 2][arow] = a0.z; As[ak + 3][arow] = a0.w;
        As[ak + 4][arow] = a1.x; As[ak + 5][arow] = a1.y;
        As[ak + 6][arow] = a1.z; As[ak + 7][arow] = a1.w;
        float4 wv = *(const float4*)&Wih[(size_t)(g0 + wrow) * EE + k0 + wk];
        Bs2[wk + 0][wrow] = make_float2(wv.x, wv.x);
        Bs2[wk + 1][wrow] = make_float2(wv.y, wv.y);
        Bs2[wk + 2][wrow] = make_float2(wv.z, wv.z);
        Bs2[wk + 3][wrow] = make_float2(wv.w, wv.w);
        __syncthreads();

        #pragma unroll
        for (int kk = 0; kk < 16; kk++) {
            u64 a0p = *(const u64*)&As[kk][0 * 32 + tx * 2];
            u64 a1p = *(const u64*)&As[kk][1 * 32 + tx * 2];
            u64 a2p = *(const u64*)&As[kk][2 * 32 + tx * 2];
            u64 a3p = *(const u64*)&As[kk][3 * 32 + tx * 2];
            u64 w0 = *(const u64*)&Bs2[kk][ty * 4 + 0];
            u64 w1 = *(const u64*)&Bs2[kk][ty * 4 + 1];
            u64 w2 = *(const u64*)&Bs2[kk][ty * 4 + 2];
            u64 w3 = *(const u64*)&Bs2[kk][ty * 4 + 3];
            cc[0][0] = fma2(a0p, w0, cc[0][0]); cc[1][0] = fma2(a1p, w0, cc[1][0]);
            cc[2][0] = fma2(a2p, w0, cc[2][0]); cc[3][0] = fma2(a3p, w0, cc[3][0]);
            cc[0][1] = fma2(a0p, w1, cc[0][1]); cc[1][1] = fma2(a1p, w1, cc[1][1]);
            cc[2][1] = fma2(a2p, w1, cc[2][1]); cc[3][1] = fma2(a3p, w1, cc[3][1]);
            cc[0][2] = fma2(a0p, w2, cc[0][2]); cc[1][2] = fma2(a1p, w2, cc[1][2]);
            cc[2][2] = fma2(a2p, w2, cc[2][2]); cc[3][2] = fma2(a3p, w2, cc[3][2]);
            cc[0][3] = fma2(a0p, w3, cc[0][3]); cc[1][3] = fma2(a1p, w3, cc[1][3]);
            cc[2][3] = fma2(a2p, w3, cc[2][3]); cc[3][3] = fma2(a3p, w3, cc[3][3]);
        }
        __syncthreads();
    }

    #pragma unroll
    for (int jn = 0; jn < 4; jn++) {
        int g = g0 + ty * 4 + jn;
        float bsum = bih[g] + bhh[g];
        #pragma unroll
        for (int p = 0; p < 4; p++) {
            float2 v = unpack2(cc[p][jn]);
            int s = s0 + (p >> 1);
            int b = (p & 1) * 32 + tx * 2;
            *(float2*)&g_xg[(size_t)s * (GG * BB) + (size_t)g * BB + b] =
                make_float2(v.x + bsum, v.y + bsum);
        }
    }
}

// ---------------------------------------------------------------------------
// Phase B: persistent LSTM recurrence, dataflow-synced (NO grid barrier).
// 128 CTAs x 256 threads (8 warps). CTA owns 4 h-columns j0..j0+3
// (8 f32x2 streams). Warp wi owns k-range [wi*64, +64) x all 64 b.
// Sync: after storing h(s), CTA release-increments g_wf[cta]. A warp at
// step s acquire-polls ONLY the 16 producer CTAs of its k-range for
// flag >= base+s (h(s-1) ready). Ring depth 4; every CTA's step-s join
// transitively covers all 128 CTAs, so slot reuse is safe. Flags are
// monotonic -> graph-replay safe. Step 0 skips the GEMM (h(-1)=0).
// SMEM: W pairs 32KB | scratch 32KB = 64KB.
// ---------------------------------------------------------------------------
__global__ void __launch_bounds__(256, 1) lstm_kernel(
    const float* __restrict__ Whh, float* __restrict__ out, int write_c)
{
    extern __shared__ float smf[];
    float*  Ws  = smf;                      // (st*512+k)*2 : {w_jA, w_jB}
    float2* scp = (float2*)(smf + 8192);    // [st8][bh2][kr8][lane32]
    __shared__ u32 s_base;

    const int tid  = threadIdx.x;
    const int wi   = tid >> 5;              // warp = k-range index (0..7)
    const int lane = tid & 31;
    const int cta  = blockIdx.x;
    const int j0   = cta * 4;
    const int kbase = wi * 64;

    if (tid == 0) s_base = g_wf[cta];       // equal across CTAs (monotonic)

    // W pairs: st = g*2+jp covers rows (g*H + j0+2jp, +1)
    #pragma unroll
    for (int st = 0; st < 8; st++) {
        int g = st >> 1, jp = st & 1;
        const float* r0 = Whh + (size_t)(g * HH + j0 + 2 * jp) * HH;
        const float* r1 = r0 + HH;
        #pragma unroll
        for (int i = 0; i < 2; i++) {
            int k = tid + i * 256;
            *(float2*)&Ws[(st * 512 + k) * 2] = make_float2(r0[k], r1[k]);
        }
    }
    __syncthreads();

    const int b  = tid & 63;        // epilogue: one (b, j) per thread
    const int jj = tid >> 6;
    const int j  = j0 + jj;
    const int jp_r  = jj >> 1;
    const int comp  = jj & 1;
    const int bh_r  = b >> 5;
    const int lane_r = b & 31;
    const u32 base = s_base;

    float c_reg = 0.f, h_val = 0.f;

    #pragma unroll 1
    for (int s = 0; s < SS; s++) {
        // xg is precomputed: load immediately, no sync needed
        float xgv[4];
        const float* xgs = g_xg + (size_t)s * (GG * BB);
        #pragma unroll
        for (int g = 0; g < 4; g++)
            xgv[g] = __ldg(&xgs[(g * HH + j) * BB + b]);

        u64 acc[8][2];
        #pragma unroll
        for (int st = 0; st < 8; st++) { acc[st][0] = 0ull; acc[st][1] = 0ull; }

        if (s > 0) {
            // wait only for the 16 producer CTAs of OUR k-range
            const u32 target = base + (u32)s;
            int ok;
            int first = 1;
            do {
                if (!first) __nanosleep(20);
                first = 0;
                ok = 1;
                if (lane < 16) {
                    u32 f;
                    asm volatile("ld.acquire.gpu.global.u32 %0, [%1];"
                                 : "=r"(f) : "l"(&g_wf[wi * 16 + lane]));
                    ok = ((int)(f - target) >= 0);
                }
            } while (__all_sync(0xffffffffu, ok) == 0);

            const float* hsrc = g_h[(s - 1) & 3];
            float hreg[2][32];
            #pragma unroll
            for (int i = 0; i < 16; i++) {
                hreg[0][i]      = __ldcg(&hsrc[(kbase + i) * 64 + lane]);
                hreg[0][16 + i] = __ldcg(&hsrc[(kbase + i) * 64 + 32 + lane]);
            }
            #pragma unroll
            for (int c = 0; c < 4; c++) {
                const int cur = c & 1, nxt = cur ^ 1;
                if (c < 3) {
                    const int kn = kbase + (c + 1) * 16;
                    #pragma unroll
                    for (int i = 0; i < 16; i++) {
                        hreg[nxt][i]      = __ldcg(&hsrc[(kn + i) * 64 + lane]);
                        hreg[nxt][16 + i] = __ldcg(&hsrc[(kn + i) * 64 + 32 + lane]);
                    }
                }
                const int kg0 = kbase + c * 16;
                #pragma unroll
                for (int kk = 0; kk < 16; kk += 2) {
                    const int kg = kg0 + kk;
                    u64 dA0 = pack2(hreg[cur][kk],          hreg[cur][kk]);
                    u64 dB0 = pack2(hreg[cur][16 + kk],     hreg[cur][16 + kk]);
                    u64 dA1 = pack2(hreg[cur][kk + 1],      hreg[cur][kk + 1]);
                    u64 dB1 = pack2(hreg[cur][16 + kk + 1], hreg[cur][16 + kk + 1]);
                    #pragma unroll
                    for (int st = 0; st < 8; st++) {
                        ulonglong2 wv = *(const ulonglong2*)&Ws[(st * 512 + kg) * 2];
                        acc[st][0] = fma2(dA0, wv.x, acc[st][0]);
                        acc[st][1] = fma2(dB0, wv.x, acc[st][1]);
                        acc[st][0] = fma2(dA1, wv.y, acc[st][0]);
                        acc[st][1] = fma2(dB1, wv.y, acc[st][1]);
                    }
                }
            }
        }

        // partials -> scratch [st][bh][kr][lane]
        #pragma unroll
        for (int st = 0; st < 8; st++) {
            scp[((st * 2 + 0) * 8 + wi) * 32 + lane] = *(float2*)&acc[st][0];
            scp[((st * 2 + 1) * 8 + wi) * 32 + lane] = *(float2*)&acc[st][1];
        }
        __syncthreads();

        // cross-warp reduce (8 k-range partials) + gates
        float gt[4];
        #pragma unroll
        for (int g = 0; g < 4; g++) {
            int st = g * 2 + jp_r;
            const float2* rb = &scp[((st * 2 + bh_r) * 8) * 32 + lane_r];
            float sx = 0.f, sy = 0.f;
            #pragma unroll
            for (int kr = 0; kr < 8; kr++) { float2 p = rb[kr * 32]; sx += p.x; sy += p.y; }
            gt[g] = (comp ? sy : sx) + xgv[g];
        }
        float ig = sigf(gt[0]), fg = sigf(gt[1]);
        float gg = tanh_f(gt[2]), og = sigf(gt[3]);
        c_reg = fg * c_reg + ig * gg;
        h_val = og * tanh_f(c_reg);

        __stcg(&g_h[s & 3][j * 64 + b], h_val);
        __syncthreads();   // all h stores of this CTA issued before flag bump
        if (tid == 0) {
            asm volatile("red.release.gpu.global.add.u32 [%0], %1;"
                         :: "l"(&g_wf[cta]), "r"(1u) : "memory");
        }
    }

    out[b * HH + j] = h_val;
    if (write_c) out[BB * HH + b * HH + j] = c_reg;
}

// ---------------------------------------------------------------------------
// kernel_launch
// ---------------------------------------------------------------------------
extern "C" void kernel_launch(void* const* d_in, const int* in_sizes, int n_in,
                              void* d_out, int out_size)
{
    const void*  seq = d_in[0];
    const float* emb = (const float*)d_in[1];
    const float* Wih = (const float*)d_in[2];
    const float* Whh = (const float*)d_in[3];
    const float* bih = (const float*)d_in[4];
    const float* bhh = (const float*)d_in[5];
    float* out = (float*)d_out;

    (void)in_sizes; (void)n_in;
    int write_c = (out_size >= 2 * BB * HH) ? 1 : 0;

    // 64 KB dynamic SMEM: W pairs 32K + scratch 32K
    static const int kSmem = (8192 + 8192) * (int)sizeof(float);
    cudaFuncSetAttribute(lstm_kernel, cudaFuncAttributeMaxDynamicSharedMemorySize, kSmem);

    xgates_gemm<<<dim3(GG / 64, SS / 2), 256>>>(seq, emb, Wih, bih, bhh);
    lstm_kernel<<<HH / 4, 256, kSmem>>>(Whh, out, write_c);
}